// round 11
// baseline (speedup 1.0000x reference)
#include <cuda_runtime.h>
#include <cstdint>

#define Tt 1024
#define Bb 64
#define Ii 512
#define Hh 1024
#define Gg 3072
#define Oo 256
#define NCTA 128

// scratch (device globals = allowed scratch)
__device__ float g_gi[(size_t)Tt * Gg * Bb];        // [t][g][b]
__device__ float g_h [(size_t)(Tt + 1) * Hh * Bb];  // [t][k][b], slot 0 = init^T
__device__ unsigned g_bar_count;

typedef unsigned long long u64;
union F4U { float4 f; u64 d[2]; };

__device__ __forceinline__ u64 pk2(float x, float y) {
    u64 r; asm("mov.b64 %0,{%1,%2};" : "=l"(r) : "f"(x), "f"(y)); return r;
}
__device__ __forceinline__ void f2(u64& d, u64 a, u64 b) {
    asm("fma.rn.f32x2 %0,%1,%2,%0;" : "+l"(d) : "l"(a), "l"(b));
}
__device__ __forceinline__ u64 add2(u64 a, u64 b) {
    u64 d; asm("add.rn.f32x2 %0,%1,%2;" : "=l"(d) : "l"(a), "l"(b)); return d;
}
__device__ __forceinline__ float2 up2(u64 a) {
    float2 f; asm("mov.b64 {%0,%1},%2;" : "=f"(f.x), "=f"(f.y) : "l"(a)); return f;
}
__device__ __forceinline__ float sigm(float x) { return 1.0f / (1.0f + __expf(-x)); }

__global__ void init_bar() { g_bar_count = 0u; }

// transpose init [b][k] -> g_h slot 0 [k][b]
__global__ void h0_init(const float* __restrict__ init) {
    int i = blockIdx.x * 256 + threadIdx.x;   // 65536
    int k = i >> 6, b = i & 63;
    g_h[(size_t)k * Bb + b] = init[(size_t)b * Hh + k];
}

// ---------------------------------------------------------------------------
// SGEMM: C[M,N] = A[M,K] @ W[K,N] + bias.  BM=128, BN=64, BK=16, 256 threads,
// thread-tile 8m x 4n (n packed as f32x2 pairs).
// MODE 0: A=X [M: b=m>>10, t=m&1023], K=512, ldw=3072, writes g_gi[t][g][b]
//         (4 scattered STG.32 per n-quad).
// MODE 1: A=g_h transposed [t][k][b] (m=t*64+b), K=1024, ldw=256, writes out.
// ---------------------------------------------------------------------------
template <int K, int MODE>
__global__ __launch_bounds__(256) void sgemm(const float* __restrict__ Ain,
                                             const float* __restrict__ W,
                                             const float* __restrict__ bias,
                                             float* __restrict__ Cout)
{
    __shared__ float As[16][132];
    __shared__ float Bs[16][64];
    const int ldw = (MODE == 0) ? Gg : Oo;
    const int m0 = blockIdx.y * 128, n0 = blockIdx.x * 64;
    const int tid = threadIdx.x;
    const int tn = tid & 15, tm = tid >> 4;

    u64 acc[8][2];
    #pragma unroll
    for (int m = 0; m < 8; m++) { acc[m][0] = 0ull; acc[m][1] = 0ull; }

    for (int k0 = 0; k0 < K; k0 += 16) {
        if (MODE == 0) {
            #pragma unroll
            for (int i = 0; i < 2; i++) {
                int idx = tid + i * 256;            // 512 float4 = 128 rows x 4
                int r = idx >> 2, kq = idx & 3;
                float4 v = *(const float4*)(Ain + (size_t)(m0 + r) * K + k0 + kq * 4);
                As[kq * 4 + 0][r] = v.x; As[kq * 4 + 1][r] = v.y;
                As[kq * 4 + 2][r] = v.z; As[kq * 4 + 3][r] = v.w;
            }
        } else {
            // tile = 2 t-slices x 16 k x 64 b from g_h[t+1][k][b]
            #pragma unroll
            for (int i = 0; i < 2; i++) {
                int idx = tid + i * 256;            // 512 float4
                int tsl = idx >> 8, k = (idx >> 4) & 15, q = idx & 15;
                float4 v = *(const float4*)(g_h +
                    (size_t)((m0 >> 6) + tsl + 1) * (Hh * Bb) + (size_t)(k0 + k) * Bb + q * 4);
                *(float4*)&As[k][tsl * 64 + q * 4] = v;
            }
        }
        {
            int r = tid >> 4, gq = tid & 15;        // 16 rows x 16 float4
            *(float4*)&Bs[r][gq * 4] =
                *(const float4*)(W + (size_t)(k0 + r) * ldw + n0 + gq * 4);
        }
        __syncthreads();
        #pragma unroll
        for (int k = 0; k < 16; k++) {
            float4 a0 = *(float4*)&As[k][tm * 8];
            float4 a1 = *(float4*)&As[k][tm * 8 + 4];
            u64 b0 = *(u64*)&Bs[k][tn * 4];
            u64 b1 = *(u64*)&Bs[k][tn * 4 + 2];
            float av[8] = {a0.x, a0.y, a0.z, a0.w, a1.x, a1.y, a1.z, a1.w};
            #pragma unroll
            for (int m = 0; m < 8; m++) {
                u64 ad = pk2(av[m], av[m]);
                f2(acc[m][0], ad, b0);
                f2(acc[m][1], ad, b1);
            }
        }
        __syncthreads();
    }

    const int n = n0 + tn * 4;
    float4 bi = *(const float4*)(bias + n);
    #pragma unroll
    for (int m = 0; m < 8; m++) {
        int r = m0 + tm * 8 + m;
        float2 p0 = up2(acc[m][0]), p1 = up2(acc[m][1]);
        float4 o = make_float4(p0.x + bi.x, p0.y + bi.y, p1.x + bi.z, p1.y + bi.w);
        if (MODE == 0) {
            int b = r >> 10, t = r & 1023;
            float* base = g_gi + (size_t)t * (Gg * Bb) + (size_t)n * Bb + b;
            base[0] = o.x; base[64] = o.y; base[128] = o.z; base[192] = o.w;
        } else {
            int t = r >> 6, b = r & 63;
            *(float4*)(Cout + ((size_t)b * Tt + t) * Oo + n) = o;
        }
    }
}

// ---------------------------------------------------------------------------
// Grid barrier: monotonic arrival counter, target = (t+1)*NCTA.
// ---------------------------------------------------------------------------
__device__ __forceinline__ void grid_bar(unsigned t1) {
    __syncthreads();
    if (threadIdx.x == 0) {
        unsigned* pc = &g_bar_count;
        asm volatile("red.add.release.gpu.u32 [%0],1;" :: "l"(pc) : "memory");
        const unsigned target = t1 * NCTA;
        unsigned g;
        do {
            asm volatile("ld.acquire.gpu.u32 %0,[%1];" : "=r"(g) : "l"(pc) : "memory");
        } while (g < target);
    }
    __syncthreads();
}

// ---------------------------------------------------------------------------
// Persistent GRU. 128 CTAs x 256 thr (8 warps). CTA owns 8 hidden units; only
// W_hh slice (96 KB) in smem. h[t-1] read DIRECTLY from L2 via __ldcg — no
// staging, no syncthreads in the k loop, no cp.async.
// Thread = (bq = warp -> b0 = bq*8 | ks = lane bits 2..4 | jp = lane bits 0..1):
//   8 batches (as 4 f32x2 PAIRS - h float4s are used as FFMA2 operands with
//   ZERO packing), units j=j0+jp*2, j+1, K 1/8-split (k = kk*8 + ks).
// Per k: 2 LDG.128(h) + 3 LDS.64(W pairs) + 6 pk2(W dup) + 24 FFMA2
//   -> 22 non-FMA issues fit the 24 gap slots: FMA-bound (12.3K cyc/SM/step).
// Reduce: 3x shfl.bfly over ks; epilogue on ks==0 lanes.
// ---------------------------------------------------------------------------
#define W_STRIDE 24
#define SMEMB (1024 * W_STRIDE * 4)

__global__ __launch_bounds__(256) void gru_persist(const float* __restrict__ Whh,
                                                   const float* __restrict__ bhh)
{
    extern __shared__ float Ws[];            // [k][g*8 + u], 1024 x 24

    const int tid = threadIdx.x;
    const int bq = tid >> 5;
    const int lane = tid & 31, ks = (lane >> 2) & 7, jp = lane & 3;
    const int b0 = bq * 8;
    const int j0 = blockIdx.x * 8, j = j0 + jp * 2;

    for (int i = tid; i < 1024 * 6; i += 256) {
        int k = i / 6, q = i - k * 6, g = q >> 1, part = q & 1;
        *(float4*)&Ws[k * W_STRIDE + g * 8 + part * 4] =
            *(const float4*)(Whh + (size_t)k * Gg + g * Hh + j0 + part * 4);
    }
    const float2 br = *(const float2*)(bhh + j);          // units j, j+1
    const float2 bz = *(const float2*)(bhh + Hh + j);
    const float2 bn = *(const float2*)(bhh + 2 * Hh + j);
    __syncthreads();

    for (int t = 0; t < Tt; ++t) {
        const float* hprev = g_h + (size_t)t * (Hh * Bb);
        float* hout       = g_h + (size_t)(t + 1) * (Hh * Bb);

        const float* hb = hprev + ks * Bb + b0;       // row k=8kk+ks, cols b0..
        const float* wp = Ws + ks * W_STRIDE + jp * 2;

        // acc[g][u][bp]: gate g, unit j+u, batch pair (b0+2bp, b0+2bp+1)
        u64 acc[3][2][4];
        #pragma unroll
        for (int g = 0; g < 3; g++)
            #pragma unroll
            for (int u = 0; u < 2; u++)
                #pragma unroll
                for (int p = 0; p < 4; p++) acc[g][u][p] = 0ull;

        #pragma unroll 4
        for (int kk = 0; kk < 128; ++kk) {
            const float* hq = hb + kk * (8 * Bb);
            F4U hA, hB;
            hA.f = __ldcg((const float4*)hq);
            hB.f = __ldcg((const float4*)(hq + 4));
            const float* wq = wp + kk * (8 * W_STRIDE);
            float2 wr = *(const float2*)(wq);
            float2 wz = *(const float2*)(wq + 8);
            float2 wn = *(const float2*)(wq + 16);
            u64 wr0 = pk2(wr.x, wr.x), wr1 = pk2(wr.y, wr.y);
            u64 wz0 = pk2(wz.x, wz.x), wz1 = pk2(wz.y, wz.y);
            u64 wn0 = pk2(wn.x, wn.x), wn1 = pk2(wn.y, wn.y);
            f2(acc[0][0][0], hA.d[0], wr0); f2(acc[0][0][1], hA.d[1], wr0);
            f2(acc[0][0][2], hB.d[0], wr0); f2(acc[0][0][3], hB.d[1], wr0);
            f2(acc[0][1][0], hA.d[0], wr1); f2(acc[0][1][1], hA.d[1], wr1);
            f2(acc[0][1][2], hB.d[0], wr1); f2(acc[0][1][3], hB.d[1], wr1);
            f2(acc[1][0][0], hA.d[0], wz0); f2(acc[1][0][1], hA.d[1], wz0);
            f2(acc[1][0][2], hB.d[0], wz0); f2(acc[1][0][3], hB.d[1], wz0);
            f2(acc[1][1][0], hA.d[0], wz1); f2(acc[1][1][1], hA.d[1], wz1);
            f2(acc[1][1][2], hB.d[0], wz1); f2(acc[1][1][3], hB.d[1], wz1);
            f2(acc[2][0][0], hA.d[0], wn0); f2(acc[2][0][1], hA.d[1], wn0);
            f2(acc[2][0][2], hB.d[0], wn0); f2(acc[2][0][3], hB.d[1], wn0);
            f2(acc[2][1][0], hA.d[0], wn1); f2(acc[2][1][1], hA.d[1], wn1);
            f2(acc[2][1][2], hB.d[0], wn1); f2(acc[2][1][3], hB.d[1], wn1);
        }

        // reduce over ks (lane bits 2..4)
        #pragma unroll
        for (int g = 0; g < 3; g++)
            #pragma unroll
            for (int u = 0; u < 2; u++)
                #pragma unroll
                for (int p = 0; p < 4; p++) {
                    u64 v = acc[g][u][p];
                    v = add2(v, __shfl_xor_sync(0xffffffffu, v, 4));
                    v = add2(v, __shfl_xor_sync(0xffffffffu, v, 8));
                    v = add2(v, __shfl_xor_sync(0xffffffffu, v, 16));
                    acc[g][u][p] = v;
                }

        if (ks == 0) {
            const float* gp = g_gi + (size_t)t * ((size_t)Gg * Bb);
            const float bias[3][2] = {{br.x, br.y}, {bz.x, bz.y}, {bn.x, bn.y}};
            #pragma unroll
            for (int u = 0; u < 2; u++) {
                const int ju = j + u;
                float ir[8], iz[8], inn[8], hp[8];
                *(float4*)&ir[0]  = __ldg((const float4*)(gp + (size_t)ju * Bb + b0));
                *(float4*)&ir[4]  = __ldg((const float4*)(gp + (size_t)ju * Bb + b0 + 4));
                *(float4*)&iz[0]  = __ldg((const float4*)(gp + (size_t)(Hh + ju) * Bb + b0));
                *(float4*)&iz[4]  = __ldg((const float4*)(gp + (size_t)(Hh + ju) * Bb + b0 + 4));
                *(float4*)&inn[0] = __ldg((const float4*)(gp + (size_t)(2 * Hh + ju) * Bb + b0));
                *(float4*)&inn[4] = __ldg((const float4*)(gp + (size_t)(2 * Hh + ju) * Bb + b0 + 4));
                *(float4*)&hp[0]  = __ldcg((const float4*)(hprev + (size_t)ju * Bb + b0));
                *(float4*)&hp[4]  = __ldcg((const float4*)(hprev + (size_t)ju * Bb + b0 + 4));
                float hn[8];
                #pragma unroll
                for (int p = 0; p < 4; p++) {
                    float2 sr = up2(acc[0][u][p]);
                    float2 sz = up2(acc[1][u][p]);
                    float2 sn = up2(acc[2][u][p]);
                    float r0 = sigm(ir[2 * p]     + sr.x + bias[0][u]);
                    float r1 = sigm(ir[2 * p + 1] + sr.y + bias[0][u]);
                    float z0 = sigm(iz[2 * p]     + sz.x + bias[1][u]);
                    float z1 = sigm(iz[2 * p + 1] + sz.y + bias[1][u]);
                    float n0 = tanhf(inn[2 * p]     + r0 * (sn.x + bias[2][u]));
                    float n1 = tanhf(inn[2 * p + 1] + r1 * (sn.y + bias[2][u]));
                    hn[2 * p]     = (1.0f - z0) * n0 + z0 * hp[2 * p];
                    hn[2 * p + 1] = (1.0f - z1) * n1 + z1 * hp[2 * p + 1];
                }
                *(float4*)(hout + (size_t)ju * Bb + b0)     = *(float4*)&hn[0];
                *(float4*)(hout + (size_t)ju * Bb + b0 + 4) = *(float4*)&hn[4];
            }
        }
        grid_bar((unsigned)(t + 1));
    }
}

extern "C" void kernel_launch(void* const* d_in, const int* in_sizes, int n_in,
                              void* d_out, int out_size)
{
    const float* X    = (const float*)d_in[0];
    const float* init = (const float*)d_in[1];
    const float* Wih  = (const float*)d_in[2];
    const float* Whh  = (const float*)d_in[3];
    const float* bih  = (const float*)d_in[4];
    const float* bhh  = (const float*)d_in[5];
    const float* Wout = (const float*)d_in[6];
    const float* bout = (const float*)d_in[7];
    float* out = (float*)d_out;

    cudaFuncSetAttribute(gru_persist,
                         cudaFuncAttributeMaxDynamicSharedMemorySize, SMEMB);

    init_bar<<<1, 1>>>();
    h0_init<<<256, 256>>>(init);

    // Phase 1: gi = X @ W_ih + b_ih   (M=65536, N=3072, K=512)
    sgemm<512, 0><<<dim3(Gg / 64, (Bb * Tt) / 128), 256>>>(X, Wih, bih, nullptr);

    // Phase 2: all 1024 GRU steps in one persistent kernel
    gru_persist<<<NCTA, 256, SMEMB>>>(Whh, bhh);

    // Phase 3: out = h @ W_out + b_out  (M=65536, N=256, K=1024)
    sgemm<1024, 1><<<dim3(Oo / 64, (Bb * Tt) / 128), 256>>>(nullptr, Wout, bout, out);
}

// round 12
// speedup vs baseline: 1.0033x; 1.0033x over previous
#include <cuda_runtime.h>
#include <cstdint>

#define Tt 1024
#define Bb 64
#define Ii 512
#define Hh 1024
#define Gg 3072
#define Oo 256
#define NCTA 128

// scratch (device globals = allowed scratch)
__device__ float g_gi[(size_t)Tt * Gg * Bb];        // [t][g][b]
__device__ float g_h [(size_t)(Tt + 1) * Hh * Bb];  // [t][k][b], slot 0 = init^T
__device__ unsigned g_bar_count;

typedef unsigned long long u64;
union F4U { float4 f; u64 d[2]; };

__device__ __forceinline__ u64 pk2(float x, float y) {
    u64 r; asm("mov.b64 %0,{%1,%2};" : "=l"(r) : "f"(x), "f"(y)); return r;
}
__device__ __forceinline__ void f2(u64& d, u64 a, u64 b) {
    asm("fma.rn.f32x2 %0,%1,%2,%0;" : "+l"(d) : "l"(a), "l"(b));
}
__device__ __forceinline__ u64 add2(u64 a, u64 b) {
    u64 d; asm("add.rn.f32x2 %0,%1,%2;" : "=l"(d) : "l"(a), "l"(b)); return d;
}
__device__ __forceinline__ float2 up2(u64 a) {
    float2 f; asm("mov.b64 {%0,%1},%2;" : "=f"(f.x), "=f"(f.y) : "l"(a)); return f;
}
__device__ __forceinline__ float sigm(float x) { return 1.0f / (1.0f + __expf(-x)); }

__global__ void init_bar() { g_bar_count = 0u; }

// transpose init [b][k] -> g_h slot 0 [k][b]
__global__ void h0_init(const float* __restrict__ init) {
    int i = blockIdx.x * 256 + threadIdx.x;   // 65536
    int k = i >> 6, b = i & 63;
    g_h[(size_t)k * Bb + b] = init[(size_t)b * Hh + k];
}

// ---------------------------------------------------------------------------
// SGEMM: C[M,N] = A[M,K] @ W[K,N] + bias.  BM=128, BN=64, BK=16, 256 threads,
// thread-tile 8m x 4n (n packed as f32x2 pairs).
// MODE 0: A=X [M: b=m>>10, t=m&1023], K=512, ldw=3072, writes g_gi[t][g][b]
//         (4 scattered STG.32 per n-quad).
// MODE 1: A=g_h transposed [t][k][b] (m=t*64+b), K=1024, ldw=256, writes out.
// ---------------------------------------------------------------------------
template <int K, int MODE>
__global__ __launch_bounds__(256) void sgemm(const float* __restrict__ Ain,
                                             const float* __restrict__ W,
                                             const float* __restrict__ bias,
                                             float* __restrict__ Cout)
{
    __shared__ float As[16][132];
    __shared__ float Bs[16][64];
    const int ldw = (MODE == 0) ? Gg : Oo;
    const int m0 = blockIdx.y * 128, n0 = blockIdx.x * 64;
    const int tid = threadIdx.x;
    const int tn = tid & 15, tm = tid >> 4;

    u64 acc[8][2];
    #pragma unroll
    for (int m = 0; m < 8; m++) { acc[m][0] = 0ull; acc[m][1] = 0ull; }

    for (int k0 = 0; k0 < K; k0 += 16) {
        if (MODE == 0) {
            #pragma unroll
            for (int i = 0; i < 2; i++) {
                int idx = tid + i * 256;            // 512 float4 = 128 rows x 4
                int r = idx >> 2, kq = idx & 3;
                float4 v = *(const float4*)(Ain + (size_t)(m0 + r) * K + k0 + kq * 4);
                As[kq * 4 + 0][r] = v.x; As[kq * 4 + 1][r] = v.y;
                As[kq * 4 + 2][r] = v.z; As[kq * 4 + 3][r] = v.w;
            }
        } else {
            // tile = 2 t-slices x 16 k x 64 b from g_h[t+1][k][b]
            #pragma unroll
            for (int i = 0; i < 2; i++) {
                int idx = tid + i * 256;            // 512 float4
                int tsl = idx >> 8, k = (idx >> 4) & 15, q = idx & 15;
                float4 v = *(const float4*)(g_h +
                    (size_t)((m0 >> 6) + tsl + 1) * (Hh * Bb) + (size_t)(k0 + k) * Bb + q * 4);
                *(float4*)&As[k][tsl * 64 + q * 4] = v;
            }
        }
        {
            int r = tid >> 4, gq = tid & 15;        // 16 rows x 16 float4
            *(float4*)&Bs[r][gq * 4] =
                *(const float4*)(W + (size_t)(k0 + r) * ldw + n0 + gq * 4);
        }
        __syncthreads();
        #pragma unroll
        for (int k = 0; k < 16; k++) {
            float4 a0 = *(float4*)&As[k][tm * 8];
            float4 a1 = *(float4*)&As[k][tm * 8 + 4];
            u64 b0 = *(u64*)&Bs[k][tn * 4];
            u64 b1 = *(u64*)&Bs[k][tn * 4 + 2];
            float av[8] = {a0.x, a0.y, a0.z, a0.w, a1.x, a1.y, a1.z, a1.w};
            #pragma unroll
            for (int m = 0; m < 8; m++) {
                u64 ad = pk2(av[m], av[m]);
                f2(acc[m][0], ad, b0);
                f2(acc[m][1], ad, b1);
            }
        }
        __syncthreads();
    }

    const int n = n0 + tn * 4;
    float4 bi = *(const float4*)(bias + n);
    #pragma unroll
    for (int m = 0; m < 8; m++) {
        int r = m0 + tm * 8 + m;
        float2 p0 = up2(acc[m][0]), p1 = up2(acc[m][1]);
        float4 o = make_float4(p0.x + bi.x, p0.y + bi.y, p1.x + bi.z, p1.y + bi.w);
        if (MODE == 0) {
            int b = r >> 10, t = r & 1023;
            float* base = g_gi + (size_t)t * (Gg * Bb) + (size_t)n * Bb + b;
            base[0] = o.x; base[64] = o.y; base[128] = o.z; base[192] = o.w;
        } else {
            int t = r >> 6, b = r & 63;
            *(float4*)(Cout + ((size_t)b * Tt + t) * Oo + n) = o;
        }
    }
}

// ---------------------------------------------------------------------------
// Grid barrier: monotonic arrival counter, target = (t+1)*NCTA.
// ---------------------------------------------------------------------------
__device__ __forceinline__ void grid_bar(unsigned t1) {
    __syncthreads();
    if (threadIdx.x == 0) {
        unsigned* pc = &g_bar_count;
        asm volatile("red.add.release.gpu.u32 [%0],1;" :: "l"(pc) : "memory");
        const unsigned target = t1 * NCTA;
        unsigned g;
        do {
            asm volatile("ld.acquire.gpu.u32 %0,[%1];" : "=r"(g) : "l"(pc) : "memory");
        } while (g < target);
    }
    __syncthreads();
}

// ---------------------------------------------------------------------------
// Persistent GRU. 128 CTAs x 256 thr (8 warps). CTA owns 8 hidden units; only
// W_hh slice (96 KB) in smem. h[t-1] read DIRECTLY from L2 via __ldcg — no
// staging, no syncthreads in the k loop, no cp.async.
// Thread = (bq = warp -> b0 = bq*8 | ks = lane bits 2..4 | jp = lane bits 0..1):
//   8 batches (as 4 f32x2 PAIRS - h float4s are used as FFMA2 operands with
//   ZERO packing), units j=j0+jp*2, j+1, K 1/8-split (k = kk*8 + ks).
// Per k: 2 LDG.128(h) + 3 LDS.64(W pairs) + 6 pk2(W dup) + 24 FFMA2
//   -> 22 non-FMA issues fit the 24 gap slots: FMA-bound (12.3K cyc/SM/step).
// Reduce: 3x shfl.bfly over ks; epilogue on ks==0 lanes.
// ---------------------------------------------------------------------------
#define W_STRIDE 24
#define SMEMB (1024 * W_STRIDE * 4)

__global__ __launch_bounds__(256) void gru_persist(const float* __restrict__ Whh,
                                                   const float* __restrict__ bhh)
{
    extern __shared__ float Ws[];            // [k][g*8 + u], 1024 x 24

    const int tid = threadIdx.x;
    const int bq = tid >> 5;
    const int lane = tid & 31, ks = (lane >> 2) & 7, jp = lane & 3;
    const int b0 = bq * 8;
    const int j0 = blockIdx.x * 8, j = j0 + jp * 2;

    for (int i = tid; i < 1024 * 6; i += 256) {
        int k = i / 6, q = i - k * 6, g = q >> 1, part = q & 1;
        *(float4*)&Ws[k * W_STRIDE + g * 8 + part * 4] =
            *(const float4*)(Whh + (size_t)k * Gg + g * Hh + j0 + part * 4);
    }
    const float2 br = *(const float2*)(bhh + j);          // units j, j+1
    const float2 bz = *(const float2*)(bhh + Hh + j);
    const float2 bn = *(const float2*)(bhh + 2 * Hh + j);
    __syncthreads();

    for (int t = 0; t < Tt; ++t) {
        const float* hprev = g_h + (size_t)t * (Hh * Bb);
        float* hout       = g_h + (size_t)(t + 1) * (Hh * Bb);

        const float* hb = hprev + ks * Bb + b0;       // row k=8kk+ks, cols b0..
        const float* wp = Ws + ks * W_STRIDE + jp * 2;

        // acc[g][u][bp]: gate g, unit j+u, batch pair (b0+2bp, b0+2bp+1)
        u64 acc[3][2][4];
        #pragma unroll
        for (int g = 0; g < 3; g++)
            #pragma unroll
            for (int u = 0; u < 2; u++)
                #pragma unroll
                for (int p = 0; p < 4; p++) acc[g][u][p] = 0ull;

        #pragma unroll 4
        for (int kk = 0; kk < 128; ++kk) {
            const float* hq = hb + kk * (8 * Bb);
            F4U hA, hB;
            hA.f = __ldcg((const float4*)hq);
            hB.f = __ldcg((const float4*)(hq + 4));
            const float* wq = wp + kk * (8 * W_STRIDE);
            float2 wr = *(const float2*)(wq);
            float2 wz = *(const float2*)(wq + 8);
            float2 wn = *(const float2*)(wq + 16);
            u64 wr0 = pk2(wr.x, wr.x), wr1 = pk2(wr.y, wr.y);
            u64 wz0 = pk2(wz.x, wz.x), wz1 = pk2(wz.y, wz.y);
            u64 wn0 = pk2(wn.x, wn.x), wn1 = pk2(wn.y, wn.y);
            f2(acc[0][0][0], hA.d[0], wr0); f2(acc[0][0][1], hA.d[1], wr0);
            f2(acc[0][0][2], hB.d[0], wr0); f2(acc[0][0][3], hB.d[1], wr0);
            f2(acc[0][1][0], hA.d[0], wr1); f2(acc[0][1][1], hA.d[1], wr1);
            f2(acc[0][1][2], hB.d[0], wr1); f2(acc[0][1][3], hB.d[1], wr1);
            f2(acc[1][0][0], hA.d[0], wz0); f2(acc[1][0][1], hA.d[1], wz0);
            f2(acc[1][0][2], hB.d[0], wz0); f2(acc[1][0][3], hB.d[1], wz0);
            f2(acc[1][1][0], hA.d[0], wz1); f2(acc[1][1][1], hA.d[1], wz1);
            f2(acc[1][1][2], hB.d[0], wz1); f2(acc[1][1][3], hB.d[1], wz1);
            f2(acc[2][0][0], hA.d[0], wn0); f2(acc[2][0][1], hA.d[1], wn0);
            f2(acc[2][0][2], hB.d[0], wn0); f2(acc[2][0][3], hB.d[1], wn0);
            f2(acc[2][1][0], hA.d[0], wn1); f2(acc[2][1][1], hA.d[1], wn1);
            f2(acc[2][1][2], hB.d[0], wn1); f2(acc[2][1][3], hB.d[1], wn1);
        }

        // reduce over ks (lane bits 2..4)
        #pragma unroll
        for (int g = 0; g < 3; g++)
            #pragma unroll
            for (int u = 0; u < 2; u++)
                #pragma unroll
                for (int p = 0; p < 4; p++) {
                    u64 v = acc[g][u][p];
                    v = add2(v, __shfl_xor_sync(0xffffffffu, v, 4));
                    v = add2(v, __shfl_xor_sync(0xffffffffu, v, 8));
                    v = add2(v, __shfl_xor_sync(0xffffffffu, v, 16));
                    acc[g][u][p] = v;
                }

        if (ks == 0) {
            const float* gp = g_gi + (size_t)t * ((size_t)Gg * Bb);
            const float bias[3][2] = {{br.x, br.y}, {bz.x, bz.y}, {bn.x, bn.y}};
            #pragma unroll
            for (int u = 0; u < 2; u++) {
                const int ju = j + u;
                float ir[8], iz[8], inn[8], hp[8];
                *(float4*)&ir[0]  = __ldg((const float4*)(gp + (size_t)ju * Bb + b0));
                *(float4*)&ir[4]  = __ldg((const float4*)(gp + (size_t)ju * Bb + b0 + 4));
                *(float4*)&iz[0]  = __ldg((const float4*)(gp + (size_t)(Hh + ju) * Bb + b0));
                *(float4*)&iz[4]  = __ldg((const float4*)(gp + (size_t)(Hh + ju) * Bb + b0 + 4));
                *(float4*)&inn[0] = __ldg((const float4*)(gp + (size_t)(2 * Hh + ju) * Bb + b0));
                *(float4*)&inn[4] = __ldg((const float4*)(gp + (size_t)(2 * Hh + ju) * Bb + b0 + 4));
                *(float4*)&hp[0]  = __ldcg((const float4*)(hprev + (size_t)ju * Bb + b0));
                *(float4*)&hp[4]  = __ldcg((const float4*)(hprev + (size_t)ju * Bb + b0 + 4));
                float hn[8];
                #pragma unroll
                for (int p = 0; p < 4; p++) {
                    float2 sr = up2(acc[0][u][p]);
                    float2 sz = up2(acc[1][u][p]);
                    float2 sn = up2(acc[2][u][p]);
                    float r0 = sigm(ir[2 * p]     + sr.x + bias[0][u]);
                    float r1 = sigm(ir[2 * p + 1] + sr.y + bias[0][u]);
                    float z0 = sigm(iz[2 * p]     + sz.x + bias[1][u]);
                    float z1 = sigm(iz[2 * p + 1] + sz.y + bias[1][u]);
                    float n0 = tanhf(inn[2 * p]     + r0 * (sn.x + bias[2][u]));
                    float n1 = tanhf(inn[2 * p + 1] + r1 * (sn.y + bias[2][u]));
                    hn[2 * p]     = (1.0f - z0) * n0 + z0 * hp[2 * p];
                    hn[2 * p + 1] = (1.0f - z1) * n1 + z1 * hp[2 * p + 1];
                }
                *(float4*)(hout + (size_t)ju * Bb + b0)     = *(float4*)&hn[0];
                *(float4*)(hout + (size_t)ju * Bb + b0 + 4) = *(float4*)&hn[4];
            }
        }
        grid_bar((unsigned)(t + 1));
    }
}

extern "C" void kernel_launch(void* const* d_in, const int* in_sizes, int n_in,
                              void* d_out, int out_size)
{
    const float* X    = (const float*)d_in[0];
    const float* init = (const float*)d_in[1];
    const float* Wih  = (const float*)d_in[2];
    const float* Whh  = (const float*)d_in[3];
    const float* bih  = (const float*)d_in[4];
    const float* bhh  = (const float*)d_in[5];
    const float* Wout = (const float*)d_in[6];
    const float* bout = (const float*)d_in[7];
    float* out = (float*)d_out;

    cudaFuncSetAttribute(gru_persist,
                         cudaFuncAttributeMaxDynamicSharedMemorySize, SMEMB);

    init_bar<<<1, 1>>>();
    h0_init<<<256, 256>>>(init);

    // Phase 1: gi = X @ W_ih + b_ih   (M=65536, N=3072, K=512)
    sgemm<512, 0><<<dim3(Gg / 64, (Bb * Tt) / 128), 256>>>(X, Wih, bih, nullptr);

    // Phase 2: all 1024 GRU steps in one persistent kernel
    gru_persist<<<NCTA, 256, SMEMB>>>(Whh, bhh);

    // Phase 3: out = h @ W_out + b_out  (M=65536, N=256, K=1024)
    sgemm<1024, 1><<<dim3(Oo / 64, (Bb * Tt) / 128), 256>>>(nullptr, Wout, bout, out);
}

// round 13
// speedup vs baseline: 1.2410x; 1.2369x over previous
#include <cuda_runtime.h>
#include <cstdint>

#define Tt 1024
#define Bb 64
#define Hh 1024
#define Gg 3072
#define Oo 256
#define NCTA 128

__device__ float g_gi[(size_t)Tt * Bb * Gg];        // [t][b][g]
__device__ float g_h [(size_t)(Tt + 1) * Hh * Bb];  // [t][k][b], slot 0 = init^T
__device__ unsigned g_flags[(Tt + 1) * 8];          // producers-done per h chunk

typedef unsigned long long u64;

__device__ __forceinline__ u64 pk2(float x, float y) {
    u64 r; asm("mov.b64 %0,{%1,%2};" : "=l"(r) : "f"(x), "f"(y)); return r;
}
__device__ __forceinline__ void f2(u64& d, u64 a, u64 b) {
    asm("fma.rn.f32x2 %0,%1,%2,%0;" : "+l"(d) : "l"(a), "l"(b));
}
__device__ __forceinline__ u64 add2(u64 a, u64 b) {
    u64 d; asm("add.rn.f32x2 %0,%1,%2;" : "=l"(d) : "l"(a), "l"(b)); return d;
}
__device__ __forceinline__ float2 up2(u64 a) {
    float2 f; asm("mov.b64 {%0,%1},%2;" : "=f"(f.x), "=f"(f.y) : "l"(a)); return f;
}
__device__ __forceinline__ float sigm(float x) { return 1.0f / (1.0f + __expf(-x)); }

__device__ __forceinline__ void cp16(void* smem, const void* g) {
    uint32_t s = (uint32_t)__cvta_generic_to_shared(smem);
    asm volatile("cp.async.cg.shared.global [%0], [%1], 16;" :: "r"(s), "l"(g));
}

__global__ void reset_flags() {
    int i = blockIdx.x * 256 + threadIdx.x;
    if (i < (Tt + 1) * 8) g_flags[i] = (i < 8) ? 16u : 0u;
}

// transpose init [b][k] -> g_h slot 0 [k][b]
__global__ void h0_init(const float* __restrict__ init) {
    int i = blockIdx.x * 256 + threadIdx.x;   // 65536
    int k = i >> 6, b = i & 63;
    g_h[(size_t)k * Bb + b] = init[(size_t)b * Hh + k];
}

// one polling lane per warp, shfl-broadcast; passes when all 16 producers done
__device__ __forceinline__ void wait_flag(int t, int c) {
    const unsigned* f = &g_flags[t * 8 + c];
    unsigned v;
    do {
        if ((threadIdx.x & 31) == 0)
            asm volatile("ld.acquire.gpu.u32 %0,[%1];" : "=r"(v) : "l"(f) : "memory");
        v = __shfl_sync(0xffffffffu, v, 0);
    } while (v < 16u);
}

// ---------------------------------------------------------------------------
// SGEMM (phases 1 & 3): C[M,N] = A[M,K] @ W[K,N] + bias. BM=128 BN=64 BK=16.
// MODE 0: A=X (m: b=m>>10,t=m&1023), writes g_gi[t][b][g].
// MODE 1: A=g_h [t][k][b] (m=t*64+b), writes out[b][t][o].
// ---------------------------------------------------------------------------
template <int K, int MODE>
__global__ __launch_bounds__(256) void sgemm(const float* __restrict__ Ain,
                                             const float* __restrict__ W,
                                             const float* __restrict__ bias,
                                             float* __restrict__ Cout)
{
    __shared__ float As[16][132];
    __shared__ float Bs[16][64];
    const int ldw = (MODE == 0) ? Gg : Oo;
    const int m0 = blockIdx.y * 128, n0 = blockIdx.x * 64;
    const int tid = threadIdx.x;
    const int tn = tid & 15, tm = tid >> 4;

    u64 acc[8][2];
    #pragma unroll
    for (int m = 0; m < 8; m++) { acc[m][0] = 0ull; acc[m][1] = 0ull; }

    for (int k0 = 0; k0 < K; k0 += 16) {
        if (MODE == 0) {
            #pragma unroll
            for (int i = 0; i < 2; i++) {
                int idx = tid + i * 256;
                int r = idx >> 2, kq = idx & 3;
                float4 v = *(const float4*)(Ain + (size_t)(m0 + r) * K + k0 + kq * 4);
                As[kq * 4 + 0][r] = v.x; As[kq * 4 + 1][r] = v.y;
                As[kq * 4 + 2][r] = v.z; As[kq * 4 + 3][r] = v.w;
            }
        } else {
            #pragma unroll
            for (int i = 0; i < 2; i++) {
                int idx = tid + i * 256;
                int tsl = idx >> 8, k = (idx >> 4) & 15, q = idx & 15;
                float4 v = *(const float4*)(g_h +
                    (size_t)((m0 >> 6) + tsl + 1) * (Hh * Bb) + (size_t)(k0 + k) * Bb + q * 4);
                *(float4*)&As[k][tsl * 64 + q * 4] = v;
            }
        }
        {
            int r = tid >> 4, gq = tid & 15;
            *(float4*)&Bs[r][gq * 4] =
                *(const float4*)(W + (size_t)(k0 + r) * ldw + n0 + gq * 4);
        }
        __syncthreads();
        #pragma unroll
        for (int k = 0; k < 16; k++) {
            float4 a0 = *(float4*)&As[k][tm * 8];
            float4 a1 = *(float4*)&As[k][tm * 8 + 4];
            u64 b0 = *(u64*)&Bs[k][tn * 4];
            u64 b1 = *(u64*)&Bs[k][tn * 4 + 2];
            float av[8] = {a0.x, a0.y, a0.z, a0.w, a1.x, a1.y, a1.z, a1.w};
            #pragma unroll
            for (int m = 0; m < 8; m++) {
                u64 ad = pk2(av[m], av[m]);
                f2(acc[m][0], ad, b0);
                f2(acc[m][1], ad, b1);
            }
        }
        __syncthreads();
    }

    const int n = n0 + tn * 4;
    float4 bi = *(const float4*)(bias + n);
    #pragma unroll
    for (int m = 0; m < 8; m++) {
        int r = m0 + tm * 8 + m;
        float2 p0 = up2(acc[m][0]), p1 = up2(acc[m][1]);
        float4 o = make_float4(p0.x + bi.x, p0.y + bi.y, p1.x + bi.z, p1.y + bi.w);
        if (MODE == 0) {
            int b = r >> 10, t = r & 1023;
            *(float4*)(g_gi + ((size_t)t * Bb + b) * Gg + n) = o;
        } else {
            int t = r >> 6, b = r & 63;
            *(float4*)(Cout + ((size_t)b * Tt + t) * Oo + n) = o;
        }
    }
}

// ---------------------------------------------------------------------------
// Persistent GRU (R7 core + per-chunk dataflow flags instead of grid barrier).
// 128 CTAs x 512 thr. CTA owns 8 units; W_hh slice (96 KB) in smem.
// Thread = (bq=tid>>5: 4 batches b0=bq*4 | ks=bits2..4: K/8 split | jp: unit
// pair). h streamed [k][b] in 8 chunks of 128 k, cp.async double-buffered;
// chunk c of slot t gated on g_flags[t][c]==16 (its 16 producer CTAs).
// ---------------------------------------------------------------------------
#define HT_STRIDE 72
#define CHUNK_K 128
#define WS_F (1024 * 24)
#define HT_F (2 * CHUNK_K * HT_STRIDE)
#define SMEMB ((WS_F + HT_F) * 4)

__global__ __launch_bounds__(512) void gru_persist(const float* __restrict__ Whh,
                                                   const float* __restrict__ bhh)
{
    extern __shared__ float sm[];
    float* Ws = sm;              // [k][g*8 + u] 1024 x 24
    float* Ht = sm + WS_F;       // [buf][k][72]

    const int tid = threadIdx.x;
    const int bq = tid >> 5, ks = (tid >> 2) & 7, jp = tid & 3;
    const int b0 = bq * 4;
    const int j0 = blockIdx.x * 8, j = j0 + jp * 2;
    const int myflag = blockIdx.x >> 4;          // chunk this CTA produces

    for (int i = tid; i < 1024 * 6; i += 512) {
        int k = i / 6, q = i - k * 6, g = q >> 1, part = q & 1;
        *(float4*)&Ws[k * 24 + g * 8 + part * 4] =
            *(const float4*)(Whh + (size_t)k * Gg + g * Hh + j0 + part * 4);
    }
    const float2 br = *(const float2*)(bhh + j);
    const float2 bz = *(const float2*)(bhh + Hh + j);
    const float2 bn = *(const float2*)(bhh + 2 * Hh + j);
    __syncthreads();

    for (int t = 0; t < Tt; ++t) {
        const float* hprev = g_h + (size_t)t * (Hh * Bb);
        float* hout       = g_h + (size_t)(t + 1) * (Hh * Bb);

        auto load_chunk = [&](int c, int buf) {
            const float* src = hprev + c * (CHUNK_K * Bb);
            float* dstb = Ht + buf * (CHUNK_K * HT_STRIDE);
            #pragma unroll
            for (int i = 0; i < 4; i++) {
                int f4 = i * 512 + tid;            // 2048 float4 = 128 k x 16
                int row = f4 >> 4, q = f4 & 15;
                cp16(dstb + row * HT_STRIDE + q * 4, src + f4 * 4);
            }
            asm volatile("cp.async.commit_group;");
        };
        wait_flag(t, 0);
        load_chunk(0, 0);

        // gi prefetch (stable data from phase 1) overlaps the k loop
        float2 gir[4], giz[4], gin[4];
        if (ks == 0) {
            const float* gp = g_gi + ((size_t)t * Bb + b0) * Gg;
            #pragma unroll
            for (int b = 0; b < 4; b++) {
                gir[b] = *(const float2*)(gp + (size_t)b * Gg + j);
                giz[b] = *(const float2*)(gp + (size_t)b * Gg + Hh + j);
                gin[b] = *(const float2*)(gp + (size_t)b * Gg + 2 * Hh + j);
            }
        }

        u64 acc[3][4];
        #pragma unroll
        for (int g = 0; g < 3; g++)
            #pragma unroll
            for (int b = 0; b < 4; b++) acc[g][b] = 0ull;

        for (int c = 0; c < 8; ++c) {
            if (c < 7) {
                wait_flag(t, c + 1);
                load_chunk(c + 1, (c + 1) & 1);
                asm volatile("cp.async.wait_group 1;");
            } else {
                asm volatile("cp.async.wait_group 0;");
            }
            __syncthreads();
            const float* hb = Ht + (c & 1) * (CHUNK_K * HT_STRIDE)
                              + ks * HT_STRIDE + b0;
            const float* wp = Ws + (c * CHUNK_K + ks) * 24 + jp * 2;
            #pragma unroll
            for (int kk = 0; kk < 16; ++kk) {
                const float* hq = hb + kk * (8 * HT_STRIDE);
                float4 h4 = *(const float4*)hq;
                u64 hd0 = pk2(h4.x, h4.x), hd1 = pk2(h4.y, h4.y);
                u64 hd2 = pk2(h4.z, h4.z), hd3 = pk2(h4.w, h4.w);
                const float* wq = wp + kk * (8 * 24);
                u64 wr = *(const u64*)(wq);
                u64 wz = *(const u64*)(wq + 8);
                u64 wn = *(const u64*)(wq + 16);
                f2(acc[0][0], hd0, wr); f2(acc[0][1], hd1, wr);
                f2(acc[0][2], hd2, wr); f2(acc[0][3], hd3, wr);
                f2(acc[1][0], hd0, wz); f2(acc[1][1], hd1, wz);
                f2(acc[1][2], hd2, wz); f2(acc[1][3], hd3, wz);
                f2(acc[2][0], hd0, wn); f2(acc[2][1], hd1, wn);
                f2(acc[2][2], hd2, wn); f2(acc[2][3], hd3, wn);
            }
            __syncthreads();
        }

        // hprev rows j,j+1 (gated data) loaded now; overlaps the shfl reduce
        float4 hpj, hpj1;
        if (ks == 0) {
            hpj  = *(const float4*)(hprev + (size_t)j * Bb + b0);
            hpj1 = *(const float4*)(hprev + (size_t)(j + 1) * Bb + b0);
        }

        #pragma unroll
        for (int g = 0; g < 3; g++)
            #pragma unroll
            for (int b = 0; b < 4; b++) {
                u64 v = acc[g][b];
                v = add2(v, __shfl_xor_sync(0xffffffffu, v, 4));
                v = add2(v, __shfl_xor_sync(0xffffffffu, v, 8));
                v = add2(v, __shfl_xor_sync(0xffffffffu, v, 16));
                acc[g][b] = v;
            }

        if (ks == 0) {
            const float hpv[2][4] = {{hpj.x, hpj.y, hpj.z, hpj.w},
                                     {hpj1.x, hpj1.y, hpj1.z, hpj1.w}};
            float hj[4], hj1[4];
            #pragma unroll
            for (int b = 0; b < 4; b++) {
                float2 sr = up2(acc[0][b]), sz = up2(acc[1][b]), sn = up2(acc[2][b]);
                float r0 = sigm(gir[b].x + sr.x + br.x);
                float r1 = sigm(gir[b].y + sr.y + br.y);
                float z0 = sigm(giz[b].x + sz.x + bz.x);
                float z1 = sigm(giz[b].y + sz.y + bz.y);
                float n0 = tanhf(gin[b].x + r0 * (sn.x + bn.x));
                float n1 = tanhf(gin[b].y + r1 * (sn.y + bn.y));
                hj[b]  = (1.0f - z0) * n0 + z0 * hpv[0][b];
                hj1[b] = (1.0f - z1) * n1 + z1 * hpv[1][b];
            }
            *(float4*)(hout + (size_t)j * Bb + b0) =
                make_float4(hj[0], hj[1], hj[2], hj[3]);
            *(float4*)(hout + (size_t)(j + 1) * Bb + b0) =
                make_float4(hj1[0], hj1[1], hj1[2], hj1[3]);
        }

        // publish: all h[t+1] rows of this CTA are visible -> one arrival
        __threadfence();
        __syncthreads();
        if (tid == 0)
            asm volatile("red.add.release.gpu.u32 [%0],1;"
                         :: "l"(&g_flags[(t + 1) * 8 + myflag]) : "memory");
    }
}

extern "C" void kernel_launch(void* const* d_in, const int* in_sizes, int n_in,
                              void* d_out, int out_size)
{
    const float* X    = (const float*)d_in[0];
    const float* init = (const float*)d_in[1];
    const float* Wih  = (const float*)d_in[2];
    const float* Whh  = (const float*)d_in[3];
    const float* bih  = (const float*)d_in[4];
    const float* bhh  = (const float*)d_in[5];
    const float* Wout = (const float*)d_in[6];
    const float* bout = (const float*)d_in[7];
    float* out = (float*)d_out;

    cudaFuncSetAttribute(gru_persist,
                         cudaFuncAttributeMaxDynamicSharedMemorySize, SMEMB);

    reset_flags<<<33, 256>>>();
    h0_init<<<256, 256>>>(init);

    sgemm<512, 0><<<dim3(Gg / 64, (Bb * Tt) / 128), 256>>>(X, Wih, bih, nullptr);
    gru_persist<<<NCTA, 512, SMEMB>>>(Whh, bhh);
    sgemm<1024, 1><<<dim3(Oo / 64, (Bb * Tt) / 128), 256>>>(nullptr, Wout, bout, out);
}

// round 14
// speedup vs baseline: 1.4314x; 1.1534x over previous
#include <cuda_runtime.h>
#include <cstdint>

#define Tt 1024
#define Bb 64
#define Hh 1024
#define Gg 3072
#define Oo 256
#define NCTA 128

__device__ float g_gi[(size_t)Tt * Bb * Gg];        // [t][b][g]
__device__ float g_h [(size_t)(Tt + 1) * Hh * Bb];  // [t][k][b], slot 0 = init^T
__device__ unsigned g_bar_count;
__device__ unsigned g_bar_gen;

typedef unsigned long long u64;

__device__ __forceinline__ u64 pk2(float x, float y) {
    u64 r; asm("mov.b64 %0,{%1,%2};" : "=l"(r) : "f"(x), "f"(y)); return r;
}
__device__ __forceinline__ void f2(u64& d, u64 a, u64 b) {
    asm("fma.rn.f32x2 %0,%1,%2,%0;" : "+l"(d) : "l"(a), "l"(b));
}
__device__ __forceinline__ u64 add2(u64 a, u64 b) {
    u64 d; asm("add.rn.f32x2 %0,%1,%2;" : "=l"(d) : "l"(a), "l"(b)); return d;
}
__device__ __forceinline__ float2 up2(u64 a) {
    float2 f; asm("mov.b64 {%0,%1},%2;" : "=f"(f.x), "=f"(f.y) : "l"(a)); return f;
}
__device__ __forceinline__ float sigm(float x) { return 1.0f / (1.0f + __expf(-x)); }

__device__ __forceinline__ void cp16(void* smem, const void* g) {
    uint32_t s = (uint32_t)__cvta_generic_to_shared(smem);
    asm volatile("cp.async.cg.shared.global [%0], [%1], 16;" :: "r"(s), "l"(g));
}

__global__ void init_bar() { g_bar_count = 0u; g_bar_gen = 0u; }

// transpose init [b][k] -> g_h slot 0 [k][b]
__global__ void h0_init(const float* __restrict__ init) {
    int i = blockIdx.x * 256 + threadIdx.x;   // 65536
    int k = i >> 6, b = i & 63;
    g_h[(size_t)k * Bb + b] = init[(size_t)b * Hh + k];
}

// ---------------------------------------------------------------------------
// SGEMM: C[M,N] = A[M,K] @ W[K,N] + bias. BM=128 BN=128 BK=16, 256 threads,
// thread tile 8m x 8n (n as 4 f32x2 pairs).
// MODE 0: A=X (m: b=m>>10,t=m&1023), K=512, writes g_gi[t][b][g].
// MODE 1: A=g_h [t][k][b] (m=t*64+b), K=1024, writes out[b][t][o].
// ---------------------------------------------------------------------------
template <int K, int MODE>
__global__ __launch_bounds__(256) void sgemm(const float* __restrict__ Ain,
                                             const float* __restrict__ W,
                                             const float* __restrict__ bias,
                                             float* __restrict__ Cout)
{
    __shared__ float As[16][132];
    __shared__ float Bs[16][132];
    const int ldw = (MODE == 0) ? Gg : Oo;
    const int m0 = blockIdx.y * 128, n0 = blockIdx.x * 128;
    const int tid = threadIdx.x;
    const int tn = tid & 15, tm = tid >> 4;

    u64 acc[8][4];
    #pragma unroll
    for (int m = 0; m < 8; m++)
        #pragma unroll
        for (int p = 0; p < 4; p++) acc[m][p] = 0ull;

    for (int k0 = 0; k0 < K; k0 += 16) {
        if (MODE == 0) {
            #pragma unroll
            for (int i = 0; i < 2; i++) {
                int idx = tid + i * 256;            // 512 f4 = 128 rows x 4
                int r = idx >> 2, kq = idx & 3;
                float4 v = *(const float4*)(Ain + (size_t)(m0 + r) * K + k0 + kq * 4);
                As[kq * 4 + 0][r] = v.x; As[kq * 4 + 1][r] = v.y;
                As[kq * 4 + 2][r] = v.z; As[kq * 4 + 3][r] = v.w;
            }
        } else {
            #pragma unroll
            for (int i = 0; i < 2; i++) {
                int idx = tid + i * 256;            // 2 t-slices x 16 k x 64 b
                int tsl = idx >> 8, k = (idx >> 4) & 15, q = idx & 15;
                float4 v = *(const float4*)(g_h +
                    (size_t)((m0 >> 6) + tsl + 1) * (Hh * Bb) + (size_t)(k0 + k) * Bb + q * 4);
                *(float4*)&As[k][tsl * 64 + q * 4] = v;
            }
        }
        #pragma unroll
        for (int i = 0; i < 2; i++) {               // 512 f4 = 16 k x 32 quads
            int idx = tid + i * 256;
            int r = idx >> 5, q = idx & 31;
            *(float4*)&Bs[r][q * 4] =
                *(const float4*)(W + (size_t)(k0 + r) * ldw + n0 + q * 4);
        }
        __syncthreads();
        #pragma unroll
        for (int k = 0; k < 16; k++) {
            float4 a0 = *(float4*)&As[k][tm * 8];
            float4 a1 = *(float4*)&As[k][tm * 8 + 4];
            u64 b0 = *(u64*)&Bs[k][tn * 8];
            u64 b1 = *(u64*)&Bs[k][tn * 8 + 2];
            u64 b2 = *(u64*)&Bs[k][tn * 8 + 4];
            u64 b3 = *(u64*)&Bs[k][tn * 8 + 6];
            float av[8] = {a0.x, a0.y, a0.z, a0.w, a1.x, a1.y, a1.z, a1.w};
            #pragma unroll
            for (int m = 0; m < 8; m++) {
                u64 ad = pk2(av[m], av[m]);
                f2(acc[m][0], ad, b0); f2(acc[m][1], ad, b1);
                f2(acc[m][2], ad, b2); f2(acc[m][3], ad, b3);
            }
        }
        __syncthreads();
    }

    const int n = n0 + tn * 8;
    float4 bi0 = *(const float4*)(bias + n);
    float4 bi1 = *(const float4*)(bias + n + 4);
    #pragma unroll
    for (int m = 0; m < 8; m++) {
        int r = m0 + tm * 8 + m;
        float2 p0 = up2(acc[m][0]), p1 = up2(acc[m][1]);
        float2 p2 = up2(acc[m][2]), p3 = up2(acc[m][3]);
        float4 o0 = make_float4(p0.x + bi0.x, p0.y + bi0.y, p1.x + bi0.z, p1.y + bi0.w);
        float4 o1 = make_float4(p2.x + bi1.x, p2.y + bi1.y, p3.x + bi1.z, p3.y + bi1.w);
        if (MODE == 0) {
            int b = r >> 10, t = r & 1023;
            float* dst = g_gi + ((size_t)t * Bb + b) * Gg + n;
            *(float4*)dst = o0; *(float4*)(dst + 4) = o1;
        } else {
            int t = r >> 6, b = r & 63;
            float* dst = Cout + ((size_t)b * Tt + t) * Oo + n;
            *(float4*)dst = o0; *(float4*)(dst + 4) = o1;
        }
    }
}

// ---------------------------------------------------------------------------
// Grid barrier (128 co-resident CTAs, 1 CTA/SM by smem footprint).
// ---------------------------------------------------------------------------
__device__ __forceinline__ void grid_bar(unsigned target) {
    __syncthreads();
    if (threadIdx.x == 0) {
        unsigned* pc = &g_bar_count;
        unsigned* pg = &g_bar_gen;
        unsigned cnt;
        asm volatile("atom.add.acq_rel.gpu.u32 %0,[%1],1;" : "=r"(cnt) : "l"(pc) : "memory");
        if (cnt == NCTA - 1) {
            *pc = 0u;
            asm volatile("red.add.release.gpu.u32 [%0],1;" :: "l"(pg) : "memory");
        } else {
            unsigned g;
            do {
                asm volatile("ld.acquire.gpu.u32 %0,[%1];" : "=r"(g) : "l"(pg) : "memory");
            } while (g < target);
        }
    }
    __syncthreads();
}

// ---------------------------------------------------------------------------
// Persistent GRU (R7 core; triple-buffered h chunks, ONE sync per chunk).
// 128 CTAs x 512 thr. CTA owns 8 units; W_hh slice (96 KB) in smem.
// Thread = (bq=tid>>5: 4 batches b0=bq*4 | ks=(tid>>2)&7: K/8 | jp=tid&3).
// Iter c: wait_group(1) [group c, issued 2 iters ago] -> sync [visibility +
// buffer (c+2)%3 free] -> issue load(c+2) -> compute chunk c.
// ---------------------------------------------------------------------------
#define HT_STRIDE 72
#define CHUNK_K 128
#define WS_F (1024 * 24)
#define HT_F (3 * CHUNK_K * HT_STRIDE)
#define SMEMB ((WS_F + HT_F) * 4)

__global__ __launch_bounds__(512) void gru_persist(const float* __restrict__ Whh,
                                                   const float* __restrict__ bhh)
{
    extern __shared__ float sm[];
    float* Ws = sm;              // [k][g*8 + u] 1024 x 24
    float* Ht = sm + WS_F;       // [buf3][k][72]

    const int tid = threadIdx.x;
    const int bq = tid >> 5, ks = (tid >> 2) & 7, jp = tid & 3;
    const int b0 = bq * 4;
    const int j0 = blockIdx.x * 8, j = j0 + jp * 2;

    for (int i = tid; i < 1024 * 6; i += 512) {
        int k = i / 6, q = i - k * 6, g = q >> 1, part = q & 1;
        *(float4*)&Ws[k * 24 + g * 8 + part * 4] =
            *(const float4*)(Whh + (size_t)k * Gg + g * Hh + j0 + part * 4);
    }
    const float2 br = *(const float2*)(bhh + j);
    const float2 bz = *(const float2*)(bhh + Hh + j);
    const float2 bn = *(const float2*)(bhh + 2 * Hh + j);
    __syncthreads();

    for (int t = 0; t < Tt; ++t) {
        const float* hprev = g_h + (size_t)t * (Hh * Bb);
        float* hout       = g_h + (size_t)(t + 1) * (Hh * Bb);

        auto load_chunk = [&](int c, int buf) {
            const float* src = hprev + c * (CHUNK_K * Bb);
            float* dstb = Ht + buf * (CHUNK_K * HT_STRIDE);
            #pragma unroll
            for (int i = 0; i < 4; i++) {
                int f4 = i * 512 + tid;            // 2048 f4 = 128 k x 16
                int row = f4 >> 4, q = f4 & 15;
                cp16(dstb + row * HT_STRIDE + q * 4, src + f4 * 4);
            }
            asm volatile("cp.async.commit_group;");
        };
        load_chunk(0, 0);
        load_chunk(1, 1);

        // epilogue operand prefetch (consumed after the k loop)
        float2 gir[4], giz[4], gin[4];
        float4 hpj, hpj1;
        if (ks == 0) {
            const float* gp = g_gi + ((size_t)t * Bb + b0) * Gg;
            #pragma unroll
            for (int b = 0; b < 4; b++) {
                gir[b] = *(const float2*)(gp + (size_t)b * Gg + j);
                giz[b] = *(const float2*)(gp + (size_t)b * Gg + Hh + j);
                gin[b] = *(const float2*)(gp + (size_t)b * Gg + 2 * Hh + j);
            }
            hpj  = *(const float4*)(hprev + (size_t)j * Bb + b0);
            hpj1 = *(const float4*)(hprev + (size_t)(j + 1) * Bb + b0);
        }

        u64 acc[3][4];
        #pragma unroll
        for (int g = 0; g < 3; g++)
            #pragma unroll
            for (int b = 0; b < 4; b++) acc[g][b] = 0ull;

        #pragma unroll 1
        for (int c = 0; c < 8; ++c) {
            if (c < 7) asm volatile("cp.async.wait_group 1;");
            else       asm volatile("cp.async.wait_group 0;");
            __syncthreads();
            if (c < 6) load_chunk(c + 2, (c + 2) % 3);
            const float* hb = Ht + (c % 3) * (CHUNK_K * HT_STRIDE)
                              + ks * HT_STRIDE + b0;
            const float* wp = Ws + (c * CHUNK_K + ks) * 24 + jp * 2;
            #pragma unroll
            for (int kk = 0; kk < 16; ++kk) {
                const float* hq = hb + kk * (8 * HT_STRIDE);
                float4 h4 = *(const float4*)hq;
                u64 hd0 = pk2(h4.x, h4.x), hd1 = pk2(h4.y, h4.y);
                u64 hd2 = pk2(h4.z, h4.z), hd3 = pk2(h4.w, h4.w);
                const float* wq = wp + kk * (8 * 24);
                u64 wr = *(const u64*)(wq);
                u64 wz = *(const u64*)(wq + 8);
                u64 wn = *(const u64*)(wq + 16);
                f2(acc[0][0], hd0, wr); f2(acc[0][1], hd1, wr);
                f2(acc[0][2], hd2, wr); f2(acc[0][3], hd3, wr);
                f2(acc[1][0], hd0, wz); f2(acc[1][1], hd1, wz);
                f2(acc[1][2], hd2, wz); f2(acc[1][3], hd3, wz);
                f2(acc[2][0], hd0, wn); f2(acc[2][1], hd1, wn);
                f2(acc[2][2], hd2, wn); f2(acc[2][3], hd3, wn);
            }
        }

        // reduce over ks (lane bits 2..4)
        #pragma unroll
        for (int g = 0; g < 3; g++)
            #pragma unroll
            for (int b = 0; b < 4; b++) {
                u64 v = acc[g][b];
                v = add2(v, __shfl_xor_sync(0xffffffffu, v, 4));
                v = add2(v, __shfl_xor_sync(0xffffffffu, v, 8));
                v = add2(v, __shfl_xor_sync(0xffffffffu, v, 16));
                acc[g][b] = v;
            }

        if (ks == 0) {
            const float hpv[2][4] = {{hpj.x, hpj.y, hpj.z, hpj.w},
                                     {hpj1.x, hpj1.y, hpj1.z, hpj1.w}};
            float hj[4], hj1[4];
            #pragma unroll
            for (int b = 0; b < 4; b++) {
                float2 sr = up2(acc[0][b]), sz = up2(acc[1][b]), sn = up2(acc[2][b]);
                float r0 = sigm(gir[b].x + sr.x + br.x);
                float r1 = sigm(gir[b].y + sr.y + br.y);
                float z0 = sigm(giz[b].x + sz.x + bz.x);
                float z1 = sigm(giz[b].y + sz.y + bz.y);
                float n0 = tanhf(gin[b].x + r0 * (sn.x + bn.x));
                float n1 = tanhf(gin[b].y + r1 * (sn.y + bn.y));
                hj[b]  = (1.0f - z0) * n0 + z0 * hpv[0][b];
                hj1[b] = (1.0f - z1) * n1 + z1 * hpv[1][b];
            }
            *(float4*)(hout + (size_t)j * Bb + b0) =
                make_float4(hj[0], hj[1], hj[2], hj[3]);
            *(float4*)(hout + (size_t)(j + 1) * Bb + b0) =
                make_float4(hj1[0], hj1[1], hj1[2], hj1[3]);
        }
        grid_bar((unsigned)(t + 1));
    }
}

extern "C" void kernel_launch(void* const* d_in, const int* in_sizes, int n_in,
                              void* d_out, int out_size)
{
    const float* X    = (const float*)d_in[0];
    const float* init = (const float*)d_in[1];
    const float* Wih  = (const float*)d_in[2];
    const float* Whh  = (const float*)d_in[3];
    const float* bih  = (const float*)d_in[4];
    const float* bhh  = (const float*)d_in[5];
    const float* Wout = (const float*)d_in[6];
    const float* bout = (const float*)d_in[7];
    float* out = (float*)d_out;

    cudaFuncSetAttribute(gru_persist,
                         cudaFuncAttributeMaxDynamicSharedMemorySize, SMEMB);

    init_bar<<<1, 1>>>();
    h0_init<<<256, 256>>>(init);

    sgemm<512, 0><<<dim3(Gg / 128, (Bb * Tt) / 128), 256>>>(X, Wih, bih, nullptr);
    gru_persist<<<NCTA, 512, SMEMB>>>(Whh, bhh);
    sgemm<1024, 1><<<dim3(Oo / 128, (Bb * Tt) / 128), 256>>>(nullptr, Wout, bout, out);
}